// round 16
// baseline (speedup 1.0000x reference)
#include <cuda_runtime.h>
#include <cstdint>

#define MARGIN 1.0f
#define MAX_TRIALS 50
#define BLK 256
#define CNT_BLK 128
#define MAIN_GRID 1184
#define MAX_B (1 << 20)
#define VEC_NB (MAX_B / (BLK * 4))         // 1024 chunk-counts (1024 elems each)

// Scratch (no allocations allowed in kernel_launch)
__device__ float g_neg_score[MAX_B];   // scores of label-0 examples, stable order
__device__ uint2 g_pos[MAX_B];         // (jb = idx*50, score bits), stable order
__device__ int   g_blockcnt[VEC_NB];
__device__ int   g_num_neg;
__device__ int   g_done;
__device__ float g_extra;
__device__ float g_harm[MAX_TRIALS];

__device__ __forceinline__ void pdl_trigger() {
    asm volatile("griddepcontrol.launch_dependents;");
}
__device__ __forceinline__ void pdl_wait() {
    asm volatile("griddepcontrol.wait;" ::: "memory");
}

// ---------------- Threefry-2x32 (exact JAX partitionable semantics) --------
__device__ __forceinline__ uint32_t rotl32(uint32_t x, int d) {
    return __funnelshift_l(x, x, d);
}

__device__ __forceinline__ uint32_t jax_random_bits32(uint32_t j) {
    const uint32_t k0 = 0u, k1 = 42u;
    const uint32_t ks2 = k0 ^ k1 ^ 0x1BD11BDAu;
    uint32_t x0 = 0u + k0;          // c0 = hi32(j) = 0
    uint32_t x1 = j + k1;           // c1 = lo32(j)
    const int R0[4] = {13, 15, 26, 6};
    const int R1[4] = {17, 29, 16, 24};
#pragma unroll
    for (int i = 0; i < 4; i++) { x0 += x1; x1 = rotl32(x1, R0[i]); x1 ^= x0; }
    x0 += k1;  x1 += ks2 + 1u;
#pragma unroll
    for (int i = 0; i < 4; i++) { x0 += x1; x1 = rotl32(x1, R1[i]); x1 ^= x0; }
    x0 += ks2; x1 += k0 + 2u;
#pragma unroll
    for (int i = 0; i < 4; i++) { x0 += x1; x1 = rotl32(x1, R0[i]); x1 ^= x0; }
    x0 += k0;  x1 += k1 + 3u;
#pragma unroll
    for (int i = 0; i < 4; i++) { x0 += x1; x1 = rotl32(x1, R1[i]); x1 ^= x0; }
    x0 += k1;  x1 += ks2 + 4u;
#pragma unroll
    for (int i = 0; i < 4; i++) { x0 += x1; x1 = rotl32(x1, R0[i]); x1 ^= x0; }
    x0 += ks2; x1 += k0 + 5u;
    return x0 ^ x1;
}

__device__ __forceinline__ float bits_to_uniform(uint32_t bits) {
    return __uint_as_float((bits >> 9) | 0x3f800000u) - 1.0f;
}

__device__ __forceinline__ float sample_neg(uint32_t j, float nnf, int num_neg) {
    float u = bits_to_uniform(jax_random_bits32(j));
    int idx = (int)(u * nnf);
    idx = min(max(idx, 0), num_neg - 1);
    return __ldg(&g_neg_score[idx]);
}

__device__ __forceinline__ float warp_weight(int t) {
    int rank = max(1, MAX_TRIALS / (t + 1));
    return __ldg(&g_harm[rank - 1]);
}

// ---------------- Pass 1: count; 1024 blocks x 128 thr, 2x int4/thread -----
__global__ void count_zeros_kernel(const int* __restrict__ labels, int B) {
    int tid = threadIdx.x;
    int base = blockIdx.x * 1024;
    int c = 0;
    int e1 = base + tid * 4;
    int e2 = base + 512 + tid * 4;
    if (e2 + 3 < B) {
        int4 a = __ldg((const int4*)(labels + e1));
        int4 b = __ldg((const int4*)(labels + e2));
        c  = (a.x == 0) + (a.y == 0) + (a.z == 0) + (a.w == 0);
        c += (b.x == 0) + (b.y == 0) + (b.z == 0) + (b.w == 0);
    } else {
        for (int q = 0; q < 4; q++) {
            if (e1 + q < B && labels[e1 + q] == 0) c++;
            if (e2 + q < B && labels[e2 + q] == 0) c++;
        }
    }
#pragma unroll
    for (int off = 16; off > 0; off >>= 1)
        c += __shfl_down_sync(0xffffffffu, c, off);
    __shared__ int wsum[CNT_BLK / 32];
    if ((tid & 31) == 0) wsum[tid >> 5] = c;
    __syncthreads();
    if (tid == 0) {
        int s = 0;
#pragma unroll
        for (int w = 0; w < CNT_BLK / 32; w++) s += wsum[w];
        g_blockcnt[blockIdx.x] = s;
        if (blockIdx.x == 0) {
            g_extra = 0.0f;
            float h = 0.0f;
#pragma unroll
            for (int j = 1; j <= MAX_TRIALS; j++) {
                h += __fdiv_rn(1.0f, (float)j);
                g_harm[j - 1] = h;
            }
        }
        __threadfence();
    }
    __syncthreads();
    pdl_trigger();
}

// ---------------- Pass 2: vec4 scatter (PDL: loads before wait) ------------
__global__ void scatter_kernel(const int* __restrict__ labels,
                               const float* __restrict__ scores, int B, int nb) {
    __shared__ int wtot[BLK / 32];
    __shared__ int redi[BLK];
    __shared__ int s_exc;
    __shared__ int woff[BLK / 32];
    int bid = blockIdx.x;
    int tid = threadIdx.x;
    int lane = tid & 31;
    int w = tid >> 5;
    int e0 = (bid * BLK + tid) * 4;

    // --- independent of count's output: load + local ranks -----------------
    int   lab[4];
    float sc[4];
    if (e0 + 3 < B) {
        int4   lv = __ldg((const int4*)(labels + e0));
        float4 sv = __ldg((const float4*)(scores + e0));
        lab[0] = lv.x; lab[1] = lv.y; lab[2] = lv.z; lab[3] = lv.w;
        sc[0] = sv.x; sc[1] = sv.y; sc[2] = sv.z; sc[3] = sv.w;
    } else {
        for (int k = 0; k < 4; k++) {
            lab[k] = (e0 + k < B) ? labels[e0 + k] : 1;
            sc[k]  = (e0 + k < B) ? scores[e0 + k] : 0.0f;
        }
    }
    int f[4], c = 0;
#pragma unroll
    for (int k = 0; k < 4; k++) { f[k] = (e0 + k < B && lab[k] == 0) ? 1 : 0; c += f[k]; }

    int incl = c;
#pragma unroll
    for (int off = 1; off < 32; off <<= 1) {
        int y = __shfl_up_sync(0xffffffffu, incl, off);
        if (lane >= off) incl += y;
    }
    int thr_exc = incl - c;
    if (lane == 31) wtot[w] = incl;

    // --- from here on we need count's g_blockcnt ---------------------------
    pdl_wait();

    int part = 0;
    for (int j = tid; j < bid; j += BLK) part += g_blockcnt[j];
    redi[tid] = part;
    __syncthreads();
    for (int off = BLK / 2; off > 0; off >>= 1) {
        if (tid < off) redi[tid] += redi[tid + off];
        __syncthreads();
    }
    if (tid == 0) {
        s_exc = redi[0];
        int r = 0;
#pragma unroll
        for (int k = 0; k < BLK / 32; k++) { int t = wtot[k]; woff[k] = r; r += t; }
        if (bid == nb - 1) g_num_neg = s_exc + r;
    }
    __syncthreads();

    int neg_before = s_exc + woff[w] + thr_exc;
#pragma unroll
    for (int k = 0; k < 4; k++) {
        int i = e0 + k;
        if (i < B) {
            if (f[k]) {
                g_neg_score[neg_before] = sc[k];
            } else {
                int ps = i - neg_before;
                g_pos[ps] = make_uint2((uint32_t)i * (uint32_t)MAX_TRIALS,
                                       __float_as_uint(sc[k]));
            }
        }
        neg_before += f[k];
    }
    __threadfence();
    pdl_trigger();
}

// ---------------- Main: trial-parallel loss + finalize ---------------------
__global__ __launch_bounds__(BLK) void main_kernel(float* __restrict__ out, int B) {
    __shared__ uint32_t q1_jb[1024];
    __shared__ float    q1_s[1024];
    __shared__ uint32_t q2_jb[1024];
    __shared__ float    q2_s[1024];
    __shared__ uint32_t q3_jb[256];
    __shared__ float    q3_s[256];
    __shared__ int q1n, q2n, q3n, take1, take2;
    __shared__ float red[BLK];
    __shared__ bool s_last;
    int tid = threadIdx.x;
    int lane = tid & 31;
    if (tid == 0) { q1n = 0; q2n = 0; q3n = 0; take1 = 0; take2 = 0; }
    __syncthreads();

    pdl_wait();

    int num_neg = g_num_neg;
    int num_pos = B - num_neg;
    float nnf = (float)num_neg;
    float acc = 0.0f;

    // ---- Phase 1: trial 0 for every positive (uniform, no divergence) ----
    if (num_neg > 0) {
        int stride = gridDim.x * blockDim.x;
        for (int p = blockIdx.x * blockDim.x + tid; p < num_pos; p += stride) {
            uint2 v = __ldg(&g_pos[p]);
            uint32_t jb = v.x;
            float s = __uint_as_float(v.y);
            float ns = sample_neg(jb, nnf, num_neg);
            if (ns + MARGIN > s) {
                acc += __ldg(&g_harm[MAX_TRIALS - 1]) * fmaxf(MARGIN - (s - ns), 0.0f);
            } else {
                int h = atomicAdd(&q1n, 1);
                q1_jb[h] = jb; q1_s[h] = s;
            }
        }
    }
    __syncthreads();

    // ---- Phase 2: trials 1..4 — 8 survivors/warp, 4 lanes per survivor ----
    {
        int n1 = q1n;
        int sub = lane & 3;          // which trial within group
        int t = 1 + sub;
        while (true) {
            int b;
            if (lane == 0) b = atomicAdd(&take1, 8);
            b = __shfl_sync(0xffffffffu, b, 0);
            if (b >= n1) break;
            int nrem = n1 - b;
            int sid = lane >> 2;
            bool active = (sid < nrem);
            int qi = b + (active ? sid : 0);
            uint32_t jb = q1_jb[qi];
            float s = q1_s[qi];
            float ns = active ? sample_neg(jb + (uint32_t)t, nnf, num_neg) : 0.0f;
            bool viol = active && (ns + MARGIN > s);
            unsigned m = __ballot_sync(0xffffffffu, viol);
            unsigned nib = (m >> ((lane >> 2) * 4)) & 0xFu;
            if (viol && ((nib & ((1u << sub) - 1u)) == 0u)) {
                acc += warp_weight(t) * fmaxf(MARGIN - (s - ns), 0.0f);
            }
            if (active && sub == 0 && nib == 0u) {
                int h = atomicAdd(&q2n, 1);
                q2_jb[h] = jb; q2_s[h] = s;
            }
        }
    }
    __syncthreads();

    // ---- Phase 3: trials 5..8 — same pattern on q2, heavies -> q3 ---------
    {
        int n2 = q2n;
        int sub = lane & 3;
        int t = 5 + sub;
        while (true) {
            int b;
            if (lane == 0) b = atomicAdd(&take2, 8);
            b = __shfl_sync(0xffffffffu, b, 0);
            if (b >= n2) break;
            int nrem = n2 - b;
            int sid = lane >> 2;
            bool active = (sid < nrem);
            int qi = b + (active ? sid : 0);
            uint32_t jb = q2_jb[qi];
            float s = q2_s[qi];
            float ns = active ? sample_neg(jb + (uint32_t)t, nnf, num_neg) : 0.0f;
            bool viol = active && (ns + MARGIN > s);
            unsigned m = __ballot_sync(0xffffffffu, viol);
            unsigned nib = (m >> ((lane >> 2) * 4)) & 0xFu;
            if (viol && ((nib & ((1u << sub) - 1u)) == 0u)) {
                acc += warp_weight(t) * fmaxf(MARGIN - (s - ns), 0.0f);
            }
            if (active && sub == 0 && nib == 0u) {
                int h = atomicAdd(&q3n, 1);
                if (h < 256) { q3_jb[h] = jb; q3_s[h] = s; }
            }
        }
    }
    __syncthreads();

    // ---- Phase 4: heavies — one warp per item, lanes = trials 9..40/41..49
    {
        int n3 = min(q3n, 256);
        int wd = tid >> 5;
        int nw = BLK >> 5;
        for (int h = wd; h < n3; h += nw) {
            uint32_t jb = q3_jb[h];
            float s = q3_s[h];
            int t1 = 9 + lane;
            float ns1 = sample_neg(jb + (uint32_t)t1, nnf, num_neg);
            unsigned m1 = __ballot_sync(0xffffffffu, ns1 + MARGIN > s);
            int hit_t = -1;
            float hit_ns = 0.0f;
            if (m1) {
                int lead = __ffs(m1) - 1;
                hit_t = 9 + lead;
                hit_ns = __shfl_sync(0xffffffffu, ns1, lead);
            } else {
                int t2 = 41 + lane;
                bool act = (t2 < MAX_TRIALS);
                float ns2 = act ? sample_neg(jb + (uint32_t)t2, nnf, num_neg) : 0.0f;
                unsigned m2 = __ballot_sync(0xffffffffu, act && (ns2 + MARGIN > s));
                if (m2) {
                    int lead = __ffs(m2) - 1;
                    hit_t = 41 + lead;
                    hit_ns = __shfl_sync(0xffffffffu, ns2, lead);
                }
            }
            if (lane == 0 && hit_t >= 0) {
                acc += warp_weight(hit_t) * fmaxf(MARGIN - (s - hit_ns), 0.0f);
            }
        }
    }

    // ---- block reduction -> one global atomic; last block finalizes -------
    red[tid] = acc;
    __syncthreads();
    for (int off = BLK / 2; off > 0; off >>= 1) {
        if (tid < off) red[tid] += red[tid + off];
        __syncthreads();
    }
    if (tid == 0) {
        if (red[0] != 0.0f) atomicAdd(&g_extra, red[0]);
        __threadfence();
        int t = atomicAdd(&g_done, 1);
        s_last = (t == gridDim.x - 1);
    }
    __syncthreads();
    if (s_last && tid == 0) {
        out[0] = (num_neg > 0 && num_pos > 0) ? g_extra / (float)num_pos : 0.0f;
        g_done = 0;
    }
}

extern "C" void kernel_launch(void* const* d_in, const int* in_sizes, int n_in,
                              void* d_out, int out_size) {
    const float* scores = (const float*)d_in[0];
    const int*   labels = (const int*)d_in[1];
    float* out = (float*)d_out;
    int B  = in_sizes[0];
    int nb = (B + BLK * 4 - 1) / (BLK * 4);       // 1024 scatter blocks / chunks

    count_zeros_kernel<<<nb, CNT_BLK>>>(labels, B);

    cudaLaunchAttribute attrs[1];
    attrs[0].id = cudaLaunchAttributeProgrammaticStreamSerialization;
    attrs[0].val.programmaticStreamSerializationAllowed = 1;

    {
        cudaLaunchConfig_t cfg = {};
        cfg.gridDim = dim3(nb);
        cfg.blockDim = dim3(BLK);
        cfg.attrs = attrs;
        cfg.numAttrs = 1;
        cudaLaunchKernelEx(&cfg, scatter_kernel, labels, scores, B, nb);
    }
    {
        cudaLaunchConfig_t cfg = {};
        cfg.gridDim = dim3(MAIN_GRID);
        cfg.blockDim = dim3(BLK);
        cfg.attrs = attrs;
        cfg.numAttrs = 1;
        cudaLaunchKernelEx(&cfg, main_kernel, out, B);
    }
}

// round 17
// speedup vs baseline: 1.4632x; 1.4632x over previous
#include <cuda_runtime.h>
#include <cstdint>

#define MARGIN 1.0f
#define MAX_TRIALS 50
#define BLK 256
#define CNT_BLK 128
#define MAIN_GRID 1184
#define MAX_B (1 << 20)
#define VEC_NB (MAX_B / (BLK * 4))         // 1024 chunk-counts (1024 elems each)

// Scratch (no allocations allowed in kernel_launch)
__device__ float g_neg_score[MAX_B];   // scores of label-0 examples, stable order
__device__ uint2 g_pos[MAX_B];         // (jb = idx*50, score bits), stable order
__device__ int   g_blockcnt[VEC_NB];
__device__ int   g_num_neg;
__device__ int   g_done;
__device__ float g_extra;
__device__ float g_harm[MAX_TRIALS];

// ---------------- Threefry-2x32 (exact JAX partitionable semantics) --------
__device__ __forceinline__ uint32_t rotl32(uint32_t x, int d) {
    return __funnelshift_l(x, x, d);
}

__device__ __forceinline__ uint32_t jax_random_bits32(uint32_t j) {
    const uint32_t k0 = 0u, k1 = 42u;
    const uint32_t ks2 = k0 ^ k1 ^ 0x1BD11BDAu;
    uint32_t x0 = 0u + k0;          // c0 = hi32(j) = 0
    uint32_t x1 = j + k1;           // c1 = lo32(j)
    const int R0[4] = {13, 15, 26, 6};
    const int R1[4] = {17, 29, 16, 24};
#pragma unroll
    for (int i = 0; i < 4; i++) { x0 += x1; x1 = rotl32(x1, R0[i]); x1 ^= x0; }
    x0 += k1;  x1 += ks2 + 1u;
#pragma unroll
    for (int i = 0; i < 4; i++) { x0 += x1; x1 = rotl32(x1, R1[i]); x1 ^= x0; }
    x0 += ks2; x1 += k0 + 2u;
#pragma unroll
    for (int i = 0; i < 4; i++) { x0 += x1; x1 = rotl32(x1, R0[i]); x1 ^= x0; }
    x0 += k0;  x1 += k1 + 3u;
#pragma unroll
    for (int i = 0; i < 4; i++) { x0 += x1; x1 = rotl32(x1, R1[i]); x1 ^= x0; }
    x0 += k1;  x1 += ks2 + 4u;
#pragma unroll
    for (int i = 0; i < 4; i++) { x0 += x1; x1 = rotl32(x1, R0[i]); x1 ^= x0; }
    x0 += ks2; x1 += k0 + 5u;
    return x0 ^ x1;
}

__device__ __forceinline__ float bits_to_uniform(uint32_t bits) {
    return __uint_as_float((bits >> 9) | 0x3f800000u) - 1.0f;
}

__device__ __forceinline__ float sample_neg(uint32_t j, float nnf, int num_neg) {
    float u = bits_to_uniform(jax_random_bits32(j));
    int idx = (int)(u * nnf);
    idx = min(max(idx, 0), num_neg - 1);
    return __ldg(&g_neg_score[idx]);
}

__device__ __forceinline__ float warp_weight(int t) {
    int rank = max(1, MAX_TRIALS / (t + 1));
    return __ldg(&g_harm[rank - 1]);
}

// ---------------- Pass 1: count; 1024 blocks x 128 thr, 2x int4/thread -----
__global__ void count_zeros_kernel(const int* __restrict__ labels, int B) {
    int tid = threadIdx.x;
    int base = blockIdx.x * 1024;
    int c = 0;
    int e1 = base + tid * 4;
    int e2 = base + 512 + tid * 4;
    if (e2 + 3 < B) {
        int4 a = __ldg((const int4*)(labels + e1));
        int4 b = __ldg((const int4*)(labels + e2));
        c  = (a.x == 0) + (a.y == 0) + (a.z == 0) + (a.w == 0);
        c += (b.x == 0) + (b.y == 0) + (b.z == 0) + (b.w == 0);
    } else {
        for (int q = 0; q < 4; q++) {
            if (e1 + q < B && labels[e1 + q] == 0) c++;
            if (e2 + q < B && labels[e2 + q] == 0) c++;
        }
    }
#pragma unroll
    for (int off = 16; off > 0; off >>= 1)
        c += __shfl_down_sync(0xffffffffu, c, off);
    __shared__ int wsum[CNT_BLK / 32];
    if ((tid & 31) == 0) wsum[tid >> 5] = c;
    __syncthreads();
    if (tid == 0) {
        int s = 0;
#pragma unroll
        for (int w = 0; w < CNT_BLK / 32; w++) s += wsum[w];
        g_blockcnt[blockIdx.x] = s;
        if (blockIdx.x == 0) {
            g_extra = 0.0f;
            float h = 0.0f;
#pragma unroll
            for (int j = 1; j <= MAX_TRIALS; j++) {
                h += __fdiv_rn(1.0f, (float)j);
                g_harm[j - 1] = h;
            }
        }
    }
}

// ---------------- Pass 2: vec4 scatter with inline exclusive prefix --------
__global__ void scatter_kernel(const int* __restrict__ labels,
                               const float* __restrict__ scores, int B, int nb) {
    __shared__ int wtot[BLK / 32];
    __shared__ int redi[BLK];
    __shared__ int s_exc;
    __shared__ int woff[BLK / 32];
    int bid = blockIdx.x;
    int tid = threadIdx.x;
    int lane = tid & 31;
    int w = tid >> 5;
    int e0 = (bid * BLK + tid) * 4;

    int   lab[4];
    float sc[4];
    if (e0 + 3 < B) {
        int4   lv = __ldg((const int4*)(labels + e0));
        float4 sv = __ldg((const float4*)(scores + e0));
        lab[0] = lv.x; lab[1] = lv.y; lab[2] = lv.z; lab[3] = lv.w;
        sc[0] = sv.x; sc[1] = sv.y; sc[2] = sv.z; sc[3] = sv.w;
    } else {
        for (int k = 0; k < 4; k++) {
            lab[k] = (e0 + k < B) ? labels[e0 + k] : 1;
            sc[k]  = (e0 + k < B) ? scores[e0 + k] : 0.0f;
        }
    }
    int f[4], c = 0;
#pragma unroll
    for (int k = 0; k < 4; k++) { f[k] = (e0 + k < B && lab[k] == 0) ? 1 : 0; c += f[k]; }

    int incl = c;
#pragma unroll
    for (int off = 1; off < 32; off <<= 1) {
        int y = __shfl_up_sync(0xffffffffu, incl, off);
        if (lane >= off) incl += y;
    }
    int thr_exc = incl - c;
    if (lane == 31) wtot[w] = incl;

    int part = 0;
    for (int j = tid; j < bid; j += BLK) part += g_blockcnt[j];
    redi[tid] = part;
    __syncthreads();
    for (int off = BLK / 2; off > 0; off >>= 1) {
        if (tid < off) redi[tid] += redi[tid + off];
        __syncthreads();
    }
    if (tid == 0) {
        s_exc = redi[0];
        int r = 0;
#pragma unroll
        for (int k = 0; k < BLK / 32; k++) { int t = wtot[k]; woff[k] = r; r += t; }
        if (bid == nb - 1) g_num_neg = s_exc + r;
    }
    __syncthreads();

    int neg_before = s_exc + woff[w] + thr_exc;
#pragma unroll
    for (int k = 0; k < 4; k++) {
        int i = e0 + k;
        if (i < B) {
            if (f[k]) {
                g_neg_score[neg_before] = sc[k];
            } else {
                int ps = i - neg_before;
                g_pos[ps] = make_uint2((uint32_t)i * (uint32_t)MAX_TRIALS,
                                       __float_as_uint(sc[k]));
            }
        }
        neg_before += f[k];
    }
}

// ---------------- Main: trial-parallel loss + finalize ---------------------
__global__ __launch_bounds__(BLK) void main_kernel(float* __restrict__ out, int B) {
    __shared__ uint32_t q1_jb[1024];
    __shared__ float    q1_s[1024];
    __shared__ uint32_t q2_jb[1024];
    __shared__ float    q2_s[1024];
    __shared__ uint32_t q3_jb[256];
    __shared__ float    q3_s[256];
    __shared__ int q1n, q2n, q3n, take1, take2;
    __shared__ float red[BLK];
    __shared__ bool s_last;
    int tid = threadIdx.x;
    int lane = tid & 31;
    if (tid == 0) { q1n = 0; q2n = 0; q3n = 0; take1 = 0; take2 = 0; }
    __syncthreads();

    int num_neg = g_num_neg;
    int num_pos = B - num_neg;
    float nnf = (float)num_neg;
    float acc = 0.0f;

    // ---- Phase 1: trial 0 for every positive (uniform, no divergence) ----
    if (num_neg > 0) {
        int stride = gridDim.x * blockDim.x;
        for (int p = blockIdx.x * blockDim.x + tid; p < num_pos; p += stride) {
            uint2 v = __ldg(&g_pos[p]);
            uint32_t jb = v.x;
            float s = __uint_as_float(v.y);
            float ns = sample_neg(jb, nnf, num_neg);
            if (ns + MARGIN > s) {
                acc += __ldg(&g_harm[MAX_TRIALS - 1]) * fmaxf(MARGIN - (s - ns), 0.0f);
            } else {
                int h = atomicAdd(&q1n, 1);
                q1_jb[h] = jb; q1_s[h] = s;
            }
        }
    }
    __syncthreads();

    // ---- Phase 2: trials 1..4 — 8 survivors/warp, 4 lanes per survivor ----
    {
        int n1 = q1n;
        int sub = lane & 3;          // which trial within group
        int t = 1 + sub;
        while (true) {
            int b;
            if (lane == 0) b = atomicAdd(&take1, 8);
            b = __shfl_sync(0xffffffffu, b, 0);
            if (b >= n1) break;
            int nrem = n1 - b;
            int sid = lane >> 2;
            bool active = (sid < nrem);
            int qi = b + (active ? sid : 0);
            uint32_t jb = q1_jb[qi];
            float s = q1_s[qi];
            float ns = active ? sample_neg(jb + (uint32_t)t, nnf, num_neg) : 0.0f;
            bool viol = active && (ns + MARGIN > s);
            unsigned m = __ballot_sync(0xffffffffu, viol);
            unsigned nib = (m >> ((lane >> 2) * 4)) & 0xFu;
            if (viol && ((nib & ((1u << sub) - 1u)) == 0u)) {
                acc += warp_weight(t) * fmaxf(MARGIN - (s - ns), 0.0f);
            }
            if (active && sub == 0 && nib == 0u) {
                int h = atomicAdd(&q2n, 1);
                q2_jb[h] = jb; q2_s[h] = s;
            }
        }
    }
    __syncthreads();

    // ---- Phase 3: trials 5..8 — same pattern on q2, heavies -> q3 ---------
    {
        int n2 = q2n;
        int sub = lane & 3;
        int t = 5 + sub;
        while (true) {
            int b;
            if (lane == 0) b = atomicAdd(&take2, 8);
            b = __shfl_sync(0xffffffffu, b, 0);
            if (b >= n2) break;
            int nrem = n2 - b;
            int sid = lane >> 2;
            bool active = (sid < nrem);
            int qi = b + (active ? sid : 0);
            uint32_t jb = q2_jb[qi];
            float s = q2_s[qi];
            float ns = active ? sample_neg(jb + (uint32_t)t, nnf, num_neg) : 0.0f;
            bool viol = active && (ns + MARGIN > s);
            unsigned m = __ballot_sync(0xffffffffu, viol);
            unsigned nib = (m >> ((lane >> 2) * 4)) & 0xFu;
            if (viol && ((nib & ((1u << sub) - 1u)) == 0u)) {
                acc += warp_weight(t) * fmaxf(MARGIN - (s - ns), 0.0f);
            }
            if (active && sub == 0 && nib == 0u) {
                int h = atomicAdd(&q3n, 1);
                if (h < 256) { q3_jb[h] = jb; q3_s[h] = s; }
            }
        }
    }
    __syncthreads();

    // ---- Phase 4: heavies — one warp per item, lanes = trials 9..40/41..49
    {
        int n3 = min(q3n, 256);
        int wd = tid >> 5;
        int nw = BLK >> 5;
        for (int h = wd; h < n3; h += nw) {
            uint32_t jb = q3_jb[h];
            float s = q3_s[h];
            int t1 = 9 + lane;
            float ns1 = sample_neg(jb + (uint32_t)t1, nnf, num_neg);
            unsigned m1 = __ballot_sync(0xffffffffu, ns1 + MARGIN > s);
            int hit_t = -1;
            float hit_ns = 0.0f;
            if (m1) {
                int lead = __ffs(m1) - 1;
                hit_t = 9 + lead;
                hit_ns = __shfl_sync(0xffffffffu, ns1, lead);
            } else {
                int t2 = 41 + lane;
                bool act = (t2 < MAX_TRIALS);
                float ns2 = act ? sample_neg(jb + (uint32_t)t2, nnf, num_neg) : 0.0f;
                unsigned m2 = __ballot_sync(0xffffffffu, act && (ns2 + MARGIN > s));
                if (m2) {
                    int lead = __ffs(m2) - 1;
                    hit_t = 41 + lead;
                    hit_ns = __shfl_sync(0xffffffffu, ns2, lead);
                }
            }
            if (lane == 0 && hit_t >= 0) {
                acc += warp_weight(hit_t) * fmaxf(MARGIN - (s - hit_ns), 0.0f);
            }
        }
    }

    // ---- block reduction -> one global atomic; last block finalizes -------
    red[tid] = acc;
    __syncthreads();
    for (int off = BLK / 2; off > 0; off >>= 1) {
        if (tid < off) red[tid] += red[tid + off];
        __syncthreads();
    }
    if (tid == 0) {
        if (red[0] != 0.0f) atomicAdd(&g_extra, red[0]);
        __threadfence();
        int t = atomicAdd(&g_done, 1);
        s_last = (t == gridDim.x - 1);
    }
    __syncthreads();
    if (s_last && tid == 0) {
        out[0] = (num_neg > 0 && num_pos > 0) ? g_extra / (float)num_pos : 0.0f;
        g_done = 0;
    }
}

extern "C" void kernel_launch(void* const* d_in, const int* in_sizes, int n_in,
                              void* d_out, int out_size) {
    const float* scores = (const float*)d_in[0];
    const int*   labels = (const int*)d_in[1];
    float* out = (float*)d_out;
    int B  = in_sizes[0];
    int nb = (B + BLK * 4 - 1) / (BLK * 4);       // 1024 scatter blocks / chunks

    count_zeros_kernel<<<nb, CNT_BLK>>>(labels, B);
    scatter_kernel<<<nb, BLK>>>(labels, scores, B, nb);
    main_kernel<<<MAIN_GRID, BLK>>>(out, B);
}